// round 15
// baseline (speedup 1.0000x reference)
#include <cuda_runtime.h>
#include <cuda_fp16.h>
#include <cstdint>
#include <cstddef>

#define NN 50000
#define NE 800000
#define BASIS 64
#define HID 128
#define NG 512
#define SP 72            // smem stride in halves (144B rows)
#define WBLK_H 2304      // gemm kernels: halves per warp block (hi+lo) = 4608 B
#define GRID 444         // gemm kernels: 3 blocks/SM
#define GRIDE 296        // k_edge: 2 blocks/SM
// k_edge per-warp block: [0,4608) planes, [4608,6656) raw0, [6656,8704) raw1
#define EBLK 8704

// Scratch (__device__ globals per allocation rules).
__device__ __align__(256) __half g_dfeat[(size_t)NE * BASIS];   // fp16 dfeat (102MB)
__device__ __align__(256) float g_nf[(size_t)NN * BASIS];
__device__ __align__(256) float g_Ca[(size_t)NN * BASIS];
// Combined fp16 hi/lo B-fragment tables: [kc 4][nt 8][lane 32] -> uint4
__device__ __align__(256) uint4 g_fcW[1024];
__device__ __align__(256) uint4 g_dfW[1024];
__device__ __align__(256) uint4 g_cfW[1024];
__device__ __align__(256) uint4 g_W1[2048];   // two 64-col halves

__device__ __forceinline__ float fast_tanh(float v) {
    float y;
    asm("tanh.approx.f32 %0, %1;" : "=f"(y) : "f"(v));
    return y;
}
__device__ __forceinline__ void red_add_v4(float* p, float a, float b, float c, float d) {
    asm volatile("red.global.add.v4.f32 [%0], {%1, %2, %3, %4};"
                 :: "l"(p), "f"(a), "f"(b), "f"(c), "f"(d) : "memory");
}
__device__ __forceinline__ unsigned pack_h2(float x, float y) {
    __half2 h = __floats2half2_rn(x, y);
    return *reinterpret_cast<unsigned*>(&h);
}
__device__ __forceinline__ unsigned split_hi(float2 v, float2& rest) {
    __half2 h = __floats2half2_rn(v.x, v.y);
    rest.x = v.x - __low2float(h);
    rest.y = v.y - __high2float(h);
    return *reinterpret_cast<unsigned*>(&h);
}
__device__ __forceinline__ void split4(float4 v, uint2& hi, uint2& lo) {
    float2 r01, r23;
    unsigned h01 = split_hi(make_float2(v.x, v.y), r01);
    unsigned h23 = split_hi(make_float2(v.z, v.w), r23);
    hi = make_uint2(h01, h23);
    lo = make_uint2(pack_h2(r01.x, r01.y), pack_h2(r23.x, r23.y));
}
__device__ __forceinline__ void mma_fp16(float* d, const unsigned* a, unsigned bx, unsigned by) {
    asm volatile(
        "mma.sync.aligned.m16n8k16.row.col.f32.f16.f16.f32 "
        "{%0,%1,%2,%3}, {%4,%5,%6,%7}, {%8,%9}, {%0,%1,%2,%3};"
        : "+f"(d[0]), "+f"(d[1]), "+f"(d[2]), "+f"(d[3])
        : "r"(a[0]), "r"(a[1]), "r"(a[2]), "r"(a[3]), "r"(bx), "r"(by));
}
__device__ __forceinline__ void ldm_x4(uint32_t addr, unsigned r[4]) {
    asm volatile("ldmatrix.sync.aligned.m8n8.x4.shared.b16 {%0,%1,%2,%3}, [%4];"
                 : "=r"(r[0]), "=r"(r[1]), "=r"(r[2]), "=r"(r[3]) : "r"(addr));
}
__device__ __forceinline__ void cp_async8(uint32_t dst_s, const void* src) {
    asm volatile("cp.async.ca.shared.global [%0], [%1], 8;" :: "r"(dst_s), "l"(src));
}
#define CP_COMMIT()  asm volatile("cp.async.commit_group;" ::: "memory")
#define CP_WAIT(N)   asm volatile("cp.async.wait_group %0;" :: "n"(N) : "memory")

// Build combined permuted fp16 hi/lo fragment tables (out = x @ W).
__global__ void __launch_bounds__(256) k_prep(const float* __restrict__ fcW,
                                              const float* __restrict__ dfW,
                                              const float* __restrict__ cfW,
                                              const float* __restrict__ W1) {
    for (int idx = threadIdx.x; idx < 1024; idx += 256) {
        int kc = idx >> 8;
        int nt = (idx >> 5) & 7;
        int lane = idx & 31;
        int n = nt * 8 + (lane >> 2);
        int k0 = kc * 16 + (lane & 3) * 2;
        const float* Ws[3] = {fcW, dfW, cfW};
        uint4* T[3] = {g_fcW, g_dfW, g_cfW};
#pragma unroll
        for (int w = 0; w < 3; w++) {
            float w00 = Ws[w][(k0 + 0) * BASIS + n];
            float w01 = Ws[w][(k0 + 1) * BASIS + n];
            float w10 = Ws[w][(k0 + 8) * BASIS + n];
            float w11 = Ws[w][(k0 + 9) * BASIS + n];
            float2 r0, r1;
            uint4 e;
            e.x = split_hi(make_float2(w00, w01), r0);
            e.y = split_hi(make_float2(w10, w11), r1);
            e.z = pack_h2(r0.x, r0.y);
            e.w = pack_h2(r1.x, r1.y);
            T[w][idx] = e;
        }
    }
    for (int idx = threadIdx.x; idx < 2048; idx += 256) {
        int hf = idx >> 10;
        int rest = idx & 1023;
        int kc = rest >> 8;
        int nt = (rest >> 5) & 7;
        int lane = rest & 31;
        int n = hf * 64 + nt * 8 + (lane >> 2);
        int k0 = kc * 16 + (lane & 3) * 2;
        float w00 = W1[(k0 + 0) * HID + n];
        float w01 = W1[(k0 + 1) * HID + n];
        float w10 = W1[(k0 + 8) * HID + n];
        float w11 = W1[(k0 + 9) * HID + n];
        float2 r0, r1;
        uint4 e;
        e.x = split_hi(make_float2(w00, w01), r0);
        e.y = split_hi(make_float2(w10, w11), r1);
        e.z = pack_h2(r0.x, r0.y);
        e.w = pack_h2(r1.x, r1.y);
        g_W1[idx] = e;
    }
}

__global__ void __launch_bounds__(256) k_init_C(const int* __restrict__ Z,
                                                const float* __restrict__ embed,
                                                float* __restrict__ C) {
    int idx = blockIdx.x * blockDim.x + threadIdx.x;
    if (idx >= NN * BASIS) return;
    C[idx] = embed[Z[idx >> 6] * BASIS + (idx & 63)];
}

__global__ void __launch_bounds__(256) k_zero(float* __restrict__ p, int n) {
    int i = blockIdx.x * blockDim.x + threadIdx.x;
    if (i < n) p[i] = 0.0f;
}

// ---------------------------------------------------------------------------
// ldmatrix mainloop, 16-row warp tile: acc[8][4] += tile @ W (3-product fp16).
// ---------------------------------------------------------------------------
__device__ __forceinline__ void mma_mainloop(uint32_t aHi,
                                             const uint4* __restrict__ whl,
                                             int lane, float acc[8][4]) {
    uint32_t aLo = aHi + (unsigned)(1152 * 2);
#pragma unroll
    for (int kc = 0; kc < 4; kc++) {
        unsigned ah[4], al[4];
        uint32_t off = (unsigned)(kc * 16) * 2u;
        ldm_x4(aHi + off, ah);
        ldm_x4(aLo + off, al);
#pragma unroll
        for (int nt = 0; nt < 8; nt++) {
            uint4 wv = whl[(kc * 8 + nt) * 32 + lane];
            mma_fp16(acc[nt], ah, wv.x, wv.y);
            mma_fp16(acc[nt], al, wv.x, wv.y);
            mma_fp16(acc[nt], ah, wv.z, wv.w);
        }
    }
}

#define ZERO_ACC(acc)                               \
    _Pragma("unroll")                               \
    for (int nt = 0; nt < 8; nt++)                  \
        _Pragma("unroll")                           \
        for (int q = 0; q < 4; q++) acc[nt][q] = 0.0f;

// per-lane ldmatrix role: row / k-offset within the 16-row warp tile
#define LDM_ROLE(lane, rowoff, koff)                 \
    int rowoff = ((lane >> 3) & 1) * 8 + (lane & 7); \
    int koff = ((lane >> 4) & 1) * 8;

// Persistent tiled row-GEMM: out = in @ W + bias. 16-row warp tiles.
template<bool OUT_HALF>
__device__ __forceinline__ void rowgemm_body(const float* __restrict__ in,
                                             const uint4* __restrict__ gW,
                                             const float* __restrict__ bias,
                                             void* __restrict__ out,
                                             int nrows) {
    extern __shared__ char smc[];
    __half* xsh = reinterpret_cast<__half*>(smc);                 // 8 warp blocks x 4608B
    uint4* whl = reinterpret_cast<uint4*>(smc + 36864);           // [1024]
    float* bs = reinterpret_cast<float*>(smc + 36864 + 16384);    // [64]

    int t = threadIdx.x;
    int lane = t & 31;
    int w = t >> 5;
    int wblk = w * WBLK_H;
    float* fs = reinterpret_cast<float*>(smc + w * (WBLK_H * 2)); // warp-own 16x68 floats

    for (int i = t; i < 1024; i += 256) whl[i] = gW[i];
    if (t < BASIS) bs[t] = bias[t];
    __syncthreads();

    LDM_ROLE(lane, rowoff, koff)
    uint32_t aHi = (uint32_t)__cvta_generic_to_shared(xsh) +
                   (unsigned)(wblk + rowoff * SP + koff) * 2u;

    int warpId = blockIdx.x * 8 + w;
    const int NWP = GRID * 8;
    int tiles = (nrows + 15) / 16;
    const float4* in4 = reinterpret_cast<const float4*>(in);
    float4* o4 = reinterpret_cast<float4*>(out);
    uint2* o2 = reinterpret_cast<uint2*>(out);
    int r = lane >> 2, c = lane & 3;

    for (int wt = warpId; wt < tiles; wt += NWP) {
        int n0 = wt * 16;
        __syncwarp();
#pragma unroll
        for (int it = 0; it < 8; it++) {
            int j = it * 32 + lane;
            int e = j >> 4;
            int k4 = j & 15;
            float4 v = make_float4(0.f, 0.f, 0.f, 0.f);
            if (n0 + e < nrows) v = in4[(size_t)(n0 + e) * 16 + k4];
            uint2 hi, lo;
            split4(v, hi, lo);
            *reinterpret_cast<uint2*>(&xsh[wblk + e * SP + k4 * 4]) = hi;
            *reinterpret_cast<uint2*>(&xsh[wblk + 1152 + e * SP + k4 * 4]) = lo;
        }
        __syncwarp();

        float acc[8][4];
        ZERO_ACC(acc)
        mma_mainloop(aHi, whl, lane, acc);
        __syncwarp();

#pragma unroll
        for (int nt = 0; nt < 8; nt++) {
            int col = nt * 8 + 2 * c;
            float b0 = bs[col], b1 = bs[col + 1];
            *reinterpret_cast<float2*>(&fs[r * 68 + col]) =
                make_float2(acc[nt][0] + b0, acc[nt][1] + b1);
            *reinterpret_cast<float2*>(&fs[(r + 8) * 68 + col]) =
                make_float2(acc[nt][2] + b0, acc[nt][3] + b1);
        }
        __syncwarp();

#pragma unroll
        for (int it = 0; it < 8; it++) {
            int j = it * 32 + lane;
            int e = j >> 4;
            int k4 = j & 15;
            if (n0 + e < nrows) {
                float4 v = *reinterpret_cast<const float4*>(&fs[e * 68 + (k4 << 2)]);
                if (OUT_HALF) {
                    uint2 h;
                    h.x = pack_h2(v.x, v.y);
                    h.y = pack_h2(v.z, v.w);
                    o2[(size_t)(n0 + e) * 16 + k4] = h;
                } else {
                    o4[(size_t)(n0 + e) * 16 + k4] = v;
                }
            }
        }
    }
}

__global__ void __launch_bounds__(256, 3) k_dfeat(const float* __restrict__ in,
                                                  const float* __restrict__ bias,
                                                  __half* __restrict__ out) {
    rowgemm_body<true>(in, g_dfW, bias, out, NE);
}

__global__ void __launch_bounds__(256, 3) k_nodemv(const float* __restrict__ C,
                                                   const float* __restrict__ bias,
                                                   float* __restrict__ out) {
    rowgemm_body<false>(C, g_cfW, bias, out, NN);
}

// Edge kernel: C[dst] += tanh( (nf[src] * dfeat) @ fcW ), dfeat fp16,
// cp.async double-buffered dfeat prefetch. 2 blocks/SM.
__global__ void __launch_bounds__(256, 2) k_edge(const float* __restrict__ nf,
                                                 const __half* __restrict__ dfeat,
                                                 const int* __restrict__ src,
                                                 const int* __restrict__ dst,
                                                 float* __restrict__ Cout) {
    extern __shared__ char smc[];
    __half* xsh = reinterpret_cast<__half*>(smc);          // per-warp EBLK blocks
    uint4* whl = reinterpret_cast<uint4*>(smc + EBLK * 8); // [1024] at 69632

    int t = threadIdx.x;
    int lane = t & 31;
    int w = t >> 5;
    int wplane = (w * EBLK) >> 1;   // half-index of planes base

    for (int i = t; i < 1024; i += 256) whl[i] = g_fcW[i];
    __syncthreads();

    LDM_ROLE(lane, rowoff, koff)
    uint32_t smem_base = (uint32_t)__cvta_generic_to_shared(xsh);
    uint32_t aHi = smem_base + (unsigned)(wplane + rowoff * SP + koff) * 2u;
    // raw dfeat buffers (byte offsets within warp block)
    uint32_t raw0 = smem_base + (unsigned)(w * EBLK + 4608);
    uint32_t raw1 = raw0 + 2048u;
    const char* rawg0 = smc + w * EBLK + 4608;

    int warpId = blockIdx.x * 8 + w;
    const int NWP = GRIDE * 8;
    const int tiles = NE / 16;   // 50000 exact
    const float4* nf4 = reinterpret_cast<const float4*>(nf);
    int r = lane >> 2, c = lane & 3;

    // lane's fixed copy slice: er = lane>>1, half = lane&1 (16 rows x 128B; 8B per lane x 8 its)
    int wt = warpId;
    int sval = 0, dval = 0;
    int buf = 0;
    if (wt < tiles) {
        sval = src[(size_t)wt * 16 + (lane & 15)];
        dval = dst[(size_t)wt * 16 + (lane & 15)];
        // prefetch dfeat tile wt -> raw0
#pragma unroll
        for (int it = 0; it < 8; it++) {
            int j = it * 32 + lane;             // 0..255 -> 8B each = 2048B
            cp_async8(raw0 + (unsigned)j * 8u,
                      reinterpret_cast<const char*>(dfeat) + (size_t)wt * 2048 + j * 8);
        }
        CP_COMMIT();
    }
    for (; wt < tiles; wt += NWP) {
        int wn = wt + NWP;
        int sv_n = 0, dv_n = 0;
        if (wn < tiles) {
            sv_n = src[(size_t)wn * 16 + (lane & 15)];
            dv_n = dst[(size_t)wn * 16 + (lane & 15)];
            uint32_t rdst = buf ? raw0 : raw1;
#pragma unroll
            for (int it = 0; it < 8; it++) {
                int j = it * 32 + lane;
                cp_async8(rdst + (unsigned)j * 8u,
                          reinterpret_cast<const char*>(dfeat) + (size_t)wn * 2048 + j * 8);
            }
            CP_COMMIT();
            CP_WAIT(1);   // current tile's group complete
        } else {
            CP_WAIT(0);
        }
        __syncwarp();

        const uint2* rawc = reinterpret_cast<const uint2*>(rawg0 + (buf ? 2048 : 0));
#pragma unroll
        for (int it = 0; it < 8; it++) {
            int j = it * 32 + lane;
            int er = j >> 4;
            int k4 = j & 15;
            int s = __shfl_sync(0xffffffffu, sval, er);
            float4 a = nf4[(size_t)s * 16 + k4];
            uint2 bh = rawc[er * 16 + k4];
            float2 f01 = __half22float2(*reinterpret_cast<__half2*>(&bh.x));
            float2 f23 = __half22float2(*reinterpret_cast<__half2*>(&bh.y));
            float4 v = make_float4(a.x * f01.x, a.y * f01.y, a.z * f23.x, a.w * f23.y);
            uint2 hi, lo;
            split4(v, hi, lo);
            *reinterpret_cast<uint2*>(&xsh[wplane + er * SP + k4 * 4]) = hi;
            *reinterpret_cast<uint2*>(&xsh[wplane + 1152 + er * SP + k4 * 4]) = lo;
        }
        __syncwarp();

        float acc[8][4];
        ZERO_ACC(acc)
        mma_mainloop(aHi, whl, lane, acc);

        int dA = __shfl_sync(0xffffffffu, dval, r);
        int dB = __shfl_sync(0xffffffffu, dval, r + 8);
        float* pA = Cout + (size_t)dA * BASIS;
        float* pB = Cout + (size_t)dB * BASIS;
#pragma unroll
        for (int nt = 0; nt < 8; nt++) {
            float t0 = fast_tanh(acc[nt][0]);
            float t1 = fast_tanh(acc[nt][1]);
            float t2 = fast_tanh(acc[nt][2]);
            float t3 = fast_tanh(acc[nt][3]);
            float p0 = __shfl_xor_sync(0xffffffffu, t0, 1);
            float p1 = __shfl_xor_sync(0xffffffffu, t1, 1);
            float p2 = __shfl_xor_sync(0xffffffffu, t2, 1);
            float p3 = __shfl_xor_sync(0xffffffffu, t3, 1);
            if ((lane & 1) == 0) {
                int col = nt * 8 + 2 * c;   // c even here
                red_add_v4(pA + col, t0, t1, p0, p1);
                red_add_v4(pB + col, t2, t3, p2, p3);
            }
        }
        sval = sv_n;
        dval = dv_n;
        buf ^= 1;
    }
}

// Readout: out[batch[n]] += tanh(C@W1+b1)@W2 + b2
__global__ void __launch_bounds__(256, 3) k_readout(const float* __restrict__ C,
                                                    const int* __restrict__ batch,
                                                    const float* __restrict__ b1,
                                                    const float* __restrict__ W2,
                                                    const float* __restrict__ b2,
                                                    float* __restrict__ out) {
    extern __shared__ char smc[];
    __half* xsh = reinterpret_cast<__half*>(smc);
    uint4* whl = reinterpret_cast<uint4*>(smc + 36864);            // [2048]
    float4* W2s = reinterpret_cast<float4*>(smc + 36864 + 32768);  // [128]
    float* b1s = reinterpret_cast<float*>(smc + 36864 + 32768 + 2048);  // [128]

    int t = threadIdx.x;
    int lane = t & 31;
    int w = t >> 5;
    int wblk = w * WBLK_H;

    for (int i = t; i < 2048; i += 256) whl[i] = g_W1[i];
    if (t < HID) { W2s[t] = reinterpret_cast<const float4*>(W2)[t]; b1s[t] = b1[t]; }
    __syncthreads();

    LDM_ROLE(lane, rowoff, koff)
    uint32_t aHi = (uint32_t)__cvta_generic_to_shared(xsh) +
                   (unsigned)(wblk + rowoff * SP + koff) * 2u;

    float4 b2v = *reinterpret_cast<const float4*>(b2);
    int warpId = blockIdx.x * 8 + w;
    const int NWP = GRID * 8;
    int tiles = (NN + 15) / 16;
    const float4* in4 = reinterpret_cast<const float4*>(C);
    int r = lane >> 2, c = lane & 3;

    for (int wt = warpId; wt < tiles; wt += NWP) {
        int n0 = wt * 16;
        int bi = n0 + (lane & 15);
        int bval = batch[bi < NN ? bi : NN - 1];
        __syncwarp();
#pragma unroll
        for (int it = 0; it < 8; it++) {
            int j = it * 32 + lane;
            int e = j >> 4;
            int k4 = j & 15;
            float4 v = make_float4(0.f, 0.f, 0.f, 0.f);
            if (n0 + e < NN) v = in4[(size_t)(n0 + e) * 16 + k4];
            uint2 hi, lo;
            split4(v, hi, lo);
            *reinterpret_cast<uint2*>(&xsh[wblk + e * SP + k4 * 4]) = hi;
            *reinterpret_cast<uint2*>(&xsh[wblk + 1152 + e * SP + k4 * 4]) = lo;
        }
        __syncwarp();

        float o[2][4];
#pragma unroll
        for (int i = 0; i < 2; i++)
#pragma unroll
            for (int q = 0; q < 4; q++) o[i][q] = 0.0f;

#pragma unroll
        for (int hf = 0; hf < 2; hf++) {
            float acc[8][4];
            ZERO_ACC(acc)
            mma_mainloop(aHi, whl + hf * 1024, lane, acc);
#pragma unroll
            for (int nt = 0; nt < 8; nt++) {
                int col = hf * 64 + nt * 8 + 2 * c;
                float t0 = fast_tanh(acc[nt][0] + b1s[col]);
                float t1 = fast_tanh(acc[nt][1] + b1s[col + 1]);
                float t2 = fast_tanh(acc[nt][2] + b1s[col]);
                float t3 = fast_tanh(acc[nt][3] + b1s[col + 1]);
                float4 wa = W2s[col];
                float4 wc = W2s[col + 1];
                o[0][0] += t0 * wa.x + t1 * wc.x;
                o[0][1] += t0 * wa.y + t1 * wc.y;
                o[0][2] += t0 * wa.z + t1 * wc.z;
                o[0][3] += t0 * wa.w + t1 * wc.w;
                o[1][0] += t2 * wa.x + t3 * wc.x;
                o[1][1] += t2 * wa.y + t3 * wc.y;
                o[1][2] += t2 * wa.z + t3 * wc.z;
                o[1][3] += t2 * wa.w + t3 * wc.w;
            }
        }
#pragma unroll
        for (int i = 0; i < 2; i++)
#pragma unroll
            for (int q = 0; q < 4; q++) {
                o[i][q] += __shfl_xor_sync(0xffffffffu, o[i][q], 1);
                o[i][q] += __shfl_xor_sync(0xffffffffu, o[i][q], 2);
            }
        int g0 = __shfl_sync(0xffffffffu, bval, r);
        int g1 = __shfl_sync(0xffffffffu, bval, r + 8);
        if (c == 0) {
            if (n0 + r < NN)
                red_add_v4(out + (size_t)g0 * 4,
                           o[0][0] + b2v.x, o[0][1] + b2v.y,
                           o[0][2] + b2v.z, o[0][3] + b2v.w);
            if (n0 + r + 8 < NN)
                red_add_v4(out + (size_t)g1 * 4,
                           o[1][0] + b2v.x, o[1][1] + b2v.y,
                           o[1][2] + b2v.z, o[1][3] + b2v.w);
        }
    }
}

extern "C" void kernel_launch(void* const* d_in, const int* in_sizes, int n_in,
                              void* d_out, int out_size) {
    const int*   Z         = (const int*)d_in[0];
    const int*   ei        = (const int*)d_in[1];
    const float* edge_attr = (const float*)d_in[2];
    const int*   batch     = (const int*)d_in[3];
    const float* embed     = (const float*)d_in[4];
    const float* cfW       = (const float*)d_in[5];
    const float* cfb       = (const float*)d_in[6];
    const float* dfW       = (const float*)d_in[7];
    const float* dfb       = (const float*)d_in[8];
    const float* fcW       = (const float*)d_in[9];
    const float* W1        = (const float*)d_in[10];
    const float* b1        = (const float*)d_in[11];
    const float* W2        = (const float*)d_in[12];
    const float* b2        = (const float*)d_in[13];
    const int* src = ei;
    const int* dst = ei + NE;

    float *Ca, *nf;
    __half* dfeat;
    cudaGetSymbolAddress((void**)&Ca, g_Ca);
    cudaGetSymbolAddress((void**)&nf, g_nf);
    cudaGetSymbolAddress((void**)&dfeat, g_dfeat);

    const int SM_GEMM = 36864 + 16384 + 256;            // 53504
    const int SM_EDGE = EBLK * 8 + 16384;                // 86016
    const int SM_RO   = 36864 + 32768 + 2048 + 512;      // 72192
    cudaFuncSetAttribute(k_dfeat, cudaFuncAttributeMaxDynamicSharedMemorySize, SM_GEMM);
    cudaFuncSetAttribute(k_nodemv, cudaFuncAttributeMaxDynamicSharedMemorySize, SM_GEMM);
    cudaFuncSetAttribute(k_edge, cudaFuncAttributeMaxDynamicSharedMemorySize, SM_EDGE);
    cudaFuncSetAttribute(k_readout, cudaFuncAttributeMaxDynamicSharedMemorySize, SM_RO);

    k_prep<<<1, 256>>>(fcW, dfW, cfW, W1);
    k_init_C<<<(NN * BASIS + 255) / 256, 256>>>(Z, embed, Ca);
    k_dfeat<<<GRID, 256, SM_GEMM>>>(edge_attr, dfb, dfeat);

    for (int t = 0; t < 3; t++) {
        k_nodemv<<<GRID, 256, SM_GEMM>>>(Ca, cfb, nf);
        k_edge<<<GRIDE, 256, SM_EDGE>>>(nf, dfeat, src, dst, Ca);
    }

    k_zero<<<(NG * 4 + 255) / 256, 256>>>((float*)d_out, NG * 4);
    k_readout<<<GRID, 256, SM_RO>>>(Ca, batch, b1, W2, b2, (float*)d_out);
}

// round 16
// speedup vs baseline: 1.1084x; 1.1084x over previous
#include <cuda_runtime.h>
#include <cuda_fp16.h>
#include <cstdint>
#include <cstddef>

#define NN 50000
#define NE 800000
#define BASIS 64
#define HID 128
#define NG 512
#define SP 72            // smem stride in halves (144B rows)
#define WBLK_H 2304      // halves per warp block (hi 1152 + lo 1152) = 4608 bytes
#define GRID 444         // persistent: 3 blocks per SM

// Scratch (__device__ globals per allocation rules).
__device__ __align__(256) __half g_dfeat[(size_t)NE * BASIS];   // fp16 dfeat (102MB)
__device__ __align__(256) float g_nf[(size_t)NN * BASIS];
__device__ __align__(256) float g_Ca[(size_t)NN * BASIS];
// fp16 hi/lo B-fragment tables: [kc 4][nt 8][lane 32] -> uint4 {bh.x,bh.y,bl.x,bl.y}
__device__ __align__(256) uint4 g_dfW[1024];
__device__ __align__(256) uint4 g_cfW[1024];
__device__ __align__(256) uint4 g_W1[2048];   // two 64-col halves
// fcW hi-only table for 2-product edge GEMM: uint2 {bh.x,bh.y}
__device__ __align__(256) uint2 g_fcW2[1024];

__device__ __forceinline__ float fast_tanh(float v) {
    float y;
    asm("tanh.approx.f32 %0, %1;" : "=f"(y) : "f"(v));
    return y;
}
__device__ __forceinline__ void red_add_v4(float* p, float a, float b, float c, float d) {
    asm volatile("red.global.add.v4.f32 [%0], {%1, %2, %3, %4};"
                 :: "l"(p), "f"(a), "f"(b), "f"(c), "f"(d) : "memory");
}
__device__ __forceinline__ unsigned pack_h2(float x, float y) {
    __half2 h = __floats2half2_rn(x, y);
    return *reinterpret_cast<unsigned*>(&h);
}
__device__ __forceinline__ unsigned split_hi(float2 v, float2& rest) {
    __half2 h = __floats2half2_rn(v.x, v.y);
    rest.x = v.x - __low2float(h);
    rest.y = v.y - __high2float(h);
    return *reinterpret_cast<unsigned*>(&h);
}
__device__ __forceinline__ void split4(float4 v, uint2& hi, uint2& lo) {
    float2 r01, r23;
    unsigned h01 = split_hi(make_float2(v.x, v.y), r01);
    unsigned h23 = split_hi(make_float2(v.z, v.w), r23);
    hi = make_uint2(h01, h23);
    lo = make_uint2(pack_h2(r01.x, r01.y), pack_h2(r23.x, r23.y));
}
__device__ __forceinline__ void mma_fp16(float* d, const unsigned* a, unsigned bx, unsigned by) {
    asm volatile(
        "mma.sync.aligned.m16n8k16.row.col.f32.f16.f16.f32 "
        "{%0,%1,%2,%3}, {%4,%5,%6,%7}, {%8,%9}, {%0,%1,%2,%3};"
        : "+f"(d[0]), "+f"(d[1]), "+f"(d[2]), "+f"(d[3])
        : "r"(a[0]), "r"(a[1]), "r"(a[2]), "r"(a[3]), "r"(bx), "r"(by));
}
__device__ __forceinline__ void ldm_x4(uint32_t addr, unsigned r[4]) {
    asm volatile("ldmatrix.sync.aligned.m8n8.x4.shared.b16 {%0,%1,%2,%3}, [%4];"
                 : "=r"(r[0]), "=r"(r[1]), "=r"(r[2]), "=r"(r[3]) : "r"(addr));
}

// Build permuted fp16 hi/lo fragment tables (out = x @ W).
__global__ void __launch_bounds__(256) k_prep(const float* __restrict__ fcW,
                                              const float* __restrict__ dfW,
                                              const float* __restrict__ cfW,
                                              const float* __restrict__ W1) {
    for (int idx = threadIdx.x; idx < 1024; idx += 256) {
        int kc = idx >> 8;
        int nt = (idx >> 5) & 7;
        int lane = idx & 31;
        int n = nt * 8 + (lane >> 2);
        int k0 = kc * 16 + (lane & 3) * 2;
        // dfW / cfW: full hi+lo tables
        const float* Ws[2] = {dfW, cfW};
        uint4* T[2] = {g_dfW, g_cfW};
#pragma unroll
        for (int w = 0; w < 2; w++) {
            float w00 = Ws[w][(k0 + 0) * BASIS + n];
            float w01 = Ws[w][(k0 + 1) * BASIS + n];
            float w10 = Ws[w][(k0 + 8) * BASIS + n];
            float w11 = Ws[w][(k0 + 9) * BASIS + n];
            float2 r0, r1;
            uint4 e;
            e.x = split_hi(make_float2(w00, w01), r0);
            e.y = split_hi(make_float2(w10, w11), r1);
            e.z = pack_h2(r0.x, r0.y);
            e.w = pack_h2(r1.x, r1.y);
            T[w][idx] = e;
        }
        // fcW: hi-only table (2-product edge path)
        {
            float w00 = fcW[(k0 + 0) * BASIS + n];
            float w01 = fcW[(k0 + 1) * BASIS + n];
            float w10 = fcW[(k0 + 8) * BASIS + n];
            float w11 = fcW[(k0 + 9) * BASIS + n];
            uint2 e;
            e.x = pack_h2(w00, w01);
            e.y = pack_h2(w10, w11);
            g_fcW2[idx] = e;
        }
    }
    for (int idx = threadIdx.x; idx < 2048; idx += 256) {
        int hf = idx >> 10;
        int rest = idx & 1023;
        int kc = rest >> 8;
        int nt = (rest >> 5) & 7;
        int lane = rest & 31;
        int n = hf * 64 + nt * 8 + (lane >> 2);
        int k0 = kc * 16 + (lane & 3) * 2;
        float w00 = W1[(k0 + 0) * HID + n];
        float w01 = W1[(k0 + 1) * HID + n];
        float w10 = W1[(k0 + 8) * HID + n];
        float w11 = W1[(k0 + 9) * HID + n];
        float2 r0, r1;
        uint4 e;
        e.x = split_hi(make_float2(w00, w01), r0);
        e.y = split_hi(make_float2(w10, w11), r1);
        e.z = pack_h2(r0.x, r0.y);
        e.w = pack_h2(r1.x, r1.y);
        g_W1[idx] = e;
    }
}

__global__ void __launch_bounds__(256) k_init_C(const int* __restrict__ Z,
                                                const float* __restrict__ embed,
                                                float* __restrict__ C) {
    int idx = blockIdx.x * blockDim.x + threadIdx.x;
    if (idx >= NN * BASIS) return;
    C[idx] = embed[Z[idx >> 6] * BASIS + (idx & 63)];
}

__global__ void __launch_bounds__(256) k_zero(float* __restrict__ p, int n) {
    int i = blockIdx.x * blockDim.x + threadIdx.x;
    if (i < n) p[i] = 0.0f;
}

// ---------------------------------------------------------------------------
// ldmatrix mainloops, 16-row warp tile.
// 3-product (hi/lo W tables, uint4) and 2-product (hi-only W, uint2).
// ---------------------------------------------------------------------------
__device__ __forceinline__ void mma_mainloop(uint32_t aHi,
                                             const uint4* __restrict__ whl,
                                             int lane, float acc[8][4]) {
    uint32_t aLo = aHi + (unsigned)(1152 * 2);
#pragma unroll
    for (int kc = 0; kc < 4; kc++) {
        unsigned ah[4], al[4];
        uint32_t off = (unsigned)(kc * 16) * 2u;
        ldm_x4(aHi + off, ah);
        ldm_x4(aLo + off, al);
#pragma unroll
        for (int nt = 0; nt < 8; nt++) {
            uint4 wv = whl[(kc * 8 + nt) * 32 + lane];
            mma_fp16(acc[nt], ah, wv.x, wv.y);
            mma_fp16(acc[nt], al, wv.x, wv.y);
            mma_fp16(acc[nt], ah, wv.z, wv.w);
        }
    }
}

__device__ __forceinline__ void mma_mainloop2(uint32_t aHi,
                                              const uint2* __restrict__ wh,
                                              int lane, float acc[8][4]) {
    uint32_t aLo = aHi + (unsigned)(1152 * 2);
#pragma unroll
    for (int kc = 0; kc < 4; kc++) {
        unsigned ah[4], al[4];
        uint32_t off = (unsigned)(kc * 16) * 2u;
        ldm_x4(aHi + off, ah);
        ldm_x4(aLo + off, al);
#pragma unroll
        for (int nt = 0; nt < 8; nt++) {
            uint2 wv = wh[(kc * 8 + nt) * 32 + lane];
            mma_fp16(acc[nt], ah, wv.x, wv.y);
            mma_fp16(acc[nt], al, wv.x, wv.y);
        }
    }
}

#define ZERO_ACC(acc)                               \
    _Pragma("unroll")                               \
    for (int nt = 0; nt < 8; nt++)                  \
        _Pragma("unroll")                           \
        for (int q = 0; q < 4; q++) acc[nt][q] = 0.0f;

#define LDM_ROLE(lane, rowoff, koff)                 \
    int rowoff = ((lane >> 3) & 1) * 8 + (lane & 7); \
    int koff = ((lane >> 4) & 1) * 8;

// Persistent tiled row-GEMM: out = in @ W + bias. 16-row warp tiles.
template<bool OUT_HALF>
__device__ __forceinline__ void rowgemm_body(const float* __restrict__ in,
                                             const uint4* __restrict__ gW,
                                             const float* __restrict__ bias,
                                             void* __restrict__ out,
                                             int nrows) {
    extern __shared__ char smc[];
    __half* xsh = reinterpret_cast<__half*>(smc);                 // 8 warp blocks x 4608B
    uint4* whl = reinterpret_cast<uint4*>(smc + 36864);           // [1024]
    float* bs = reinterpret_cast<float*>(smc + 36864 + 16384);    // [64]

    int t = threadIdx.x;
    int lane = t & 31;
    int w = t >> 5;
    int wblk = w * WBLK_H;
    float* fs = reinterpret_cast<float*>(smc + w * (WBLK_H * 2)); // warp-own 16x68 floats

    for (int i = t; i < 1024; i += 256) whl[i] = gW[i];
    if (t < BASIS) bs[t] = bias[t];
    __syncthreads();

    LDM_ROLE(lane, rowoff, koff)
    uint32_t aHi = (uint32_t)__cvta_generic_to_shared(xsh) +
                   (unsigned)(wblk + rowoff * SP + koff) * 2u;

    int warpId = blockIdx.x * 8 + w;
    const int NWP = GRID * 8;
    int tiles = (nrows + 15) / 16;
    const float4* in4 = reinterpret_cast<const float4*>(in);
    float4* o4 = reinterpret_cast<float4*>(out);
    uint2* o2 = reinterpret_cast<uint2*>(out);
    int r = lane >> 2, c = lane & 3;

    for (int wt = warpId; wt < tiles; wt += NWP) {
        int n0 = wt * 16;
        __syncwarp();
#pragma unroll
        for (int it = 0; it < 8; it++) {
            int j = it * 32 + lane;
            int e = j >> 4;
            int k4 = j & 15;
            float4 v = make_float4(0.f, 0.f, 0.f, 0.f);
            if (n0 + e < nrows) v = in4[(size_t)(n0 + e) * 16 + k4];
            uint2 hi, lo;
            split4(v, hi, lo);
            *reinterpret_cast<uint2*>(&xsh[wblk + e * SP + k4 * 4]) = hi;
            *reinterpret_cast<uint2*>(&xsh[wblk + 1152 + e * SP + k4 * 4]) = lo;
        }
        __syncwarp();

        float acc[8][4];
        ZERO_ACC(acc)
        mma_mainloop(aHi, whl, lane, acc);
        __syncwarp();

#pragma unroll
        for (int nt = 0; nt < 8; nt++) {
            int col = nt * 8 + 2 * c;
            float b0 = bs[col], b1 = bs[col + 1];
            *reinterpret_cast<float2*>(&fs[r * 68 + col]) =
                make_float2(acc[nt][0] + b0, acc[nt][1] + b1);
            *reinterpret_cast<float2*>(&fs[(r + 8) * 68 + col]) =
                make_float2(acc[nt][2] + b0, acc[nt][3] + b1);
        }
        __syncwarp();

#pragma unroll
        for (int it = 0; it < 8; it++) {
            int j = it * 32 + lane;
            int e = j >> 4;
            int k4 = j & 15;
            if (n0 + e < nrows) {
                float4 v = *reinterpret_cast<const float4*>(&fs[e * 68 + (k4 << 2)]);
                if (OUT_HALF) {
                    uint2 h;
                    h.x = pack_h2(v.x, v.y);
                    h.y = pack_h2(v.z, v.w);
                    o2[(size_t)(n0 + e) * 16 + k4] = h;
                } else {
                    o4[(size_t)(n0 + e) * 16 + k4] = v;
                }
            }
        }
    }
}

__global__ void __launch_bounds__(256, 3) k_dfeat(const float* __restrict__ in,
                                                  const float* __restrict__ bias,
                                                  __half* __restrict__ out) {
    rowgemm_body<true>(in, g_dfW, bias, out, NE);
}

__global__ void __launch_bounds__(256, 3) k_nodemv(const float* __restrict__ C,
                                                   const float* __restrict__ bias,
                                                   float* __restrict__ out) {
    rowgemm_body<false>(C, g_cfW, bias, out, NN);
}

// Edge kernel: C[dst] += tanh( (nf[src] * dfeat) @ fcW ), dfeat fp16,
// 2-product Markidis (fcW hi-only).
__global__ void __launch_bounds__(256, 3) k_edge(const float* __restrict__ nf,
                                                 const __half* __restrict__ dfeat,
                                                 const int* __restrict__ src,
                                                 const int* __restrict__ dst,
                                                 float* __restrict__ Cout) {
    extern __shared__ char smc[];
    __half* xsh = reinterpret_cast<__half*>(smc);
    uint2* wh = reinterpret_cast<uint2*>(smc + 36864);   // [1024] (8KB)

    int t = threadIdx.x;
    int lane = t & 31;
    int w = t >> 5;
    int wblk = w * WBLK_H;

    for (int i = t; i < 1024; i += 256) wh[i] = g_fcW2[i];
    __syncthreads();

    LDM_ROLE(lane, rowoff, koff)
    uint32_t aHi = (uint32_t)__cvta_generic_to_shared(xsh) +
                   (unsigned)(wblk + rowoff * SP + koff) * 2u;

    int warpId = blockIdx.x * 8 + w;
    const int NWP = GRID * 8;
    const int tiles = NE / 16;   // 50000 exact
    const float4* nf4 = reinterpret_cast<const float4*>(nf);
    const uint2* df2 = reinterpret_cast<const uint2*>(dfeat);
    int r = lane >> 2, c = lane & 3;

    int wt = warpId;
    int sval = 0, dval = 0;
    if (wt < tiles) {
        sval = src[(size_t)wt * 16 + (lane & 15)];
        dval = dst[(size_t)wt * 16 + (lane & 15)];
    }
    for (; wt < tiles; wt += NWP) {
        int wn = wt + NWP;
        int sv_n = 0, dv_n = 0;
        if (wn < tiles) {
            sv_n = src[(size_t)wn * 16 + (lane & 15)];
            dv_n = dst[(size_t)wn * 16 + (lane & 15)];
        }
        __syncwarp();
#pragma unroll
        for (int it = 0; it < 8; it++) {
            int j = it * 32 + lane;
            int er = j >> 4;
            int k4 = j & 15;
            int s = __shfl_sync(0xffffffffu, sval, er);
            float4 a = nf4[(size_t)s * 16 + k4];
            uint2 bh = df2[((size_t)wt * 16 + er) * 16 + k4];
            float2 f01 = __half22float2(*reinterpret_cast<__half2*>(&bh.x));
            float2 f23 = __half22float2(*reinterpret_cast<__half2*>(&bh.y));
            float4 v = make_float4(a.x * f01.x, a.y * f01.y, a.z * f23.x, a.w * f23.y);
            uint2 hi, lo;
            split4(v, hi, lo);
            *reinterpret_cast<uint2*>(&xsh[wblk + er * SP + k4 * 4]) = hi;
            *reinterpret_cast<uint2*>(&xsh[wblk + 1152 + er * SP + k4 * 4]) = lo;
        }
        __syncwarp();

        float acc[8][4];
        ZERO_ACC(acc)
        mma_mainloop2(aHi, wh, lane, acc);

        int dA = __shfl_sync(0xffffffffu, dval, r);
        int dB = __shfl_sync(0xffffffffu, dval, r + 8);
        float* pA = Cout + (size_t)dA * BASIS;
        float* pB = Cout + (size_t)dB * BASIS;
#pragma unroll
        for (int nt = 0; nt < 8; nt++) {
            float t0 = fast_tanh(acc[nt][0]);
            float t1 = fast_tanh(acc[nt][1]);
            float t2 = fast_tanh(acc[nt][2]);
            float t3 = fast_tanh(acc[nt][3]);
            float p0 = __shfl_xor_sync(0xffffffffu, t0, 1);
            float p1 = __shfl_xor_sync(0xffffffffu, t1, 1);
            float p2 = __shfl_xor_sync(0xffffffffu, t2, 1);
            float p3 = __shfl_xor_sync(0xffffffffu, t3, 1);
            if ((lane & 1) == 0) {
                int col = nt * 8 + 2 * c;   // c even here
                red_add_v4(pA + col, t0, t1, p0, p1);
                red_add_v4(pB + col, t2, t3, p2, p3);
            }
        }
        sval = sv_n;
        dval = dv_n;
    }
}

// Readout: out[batch[n]] += tanh(C@W1+b1)@W2 + b2
__global__ void __launch_bounds__(256, 3) k_readout(const float* __restrict__ C,
                                                    const int* __restrict__ batch,
                                                    const float* __restrict__ b1,
                                                    const float* __restrict__ W2,
                                                    const float* __restrict__ b2,
                                                    float* __restrict__ out) {
    extern __shared__ char smc[];
    __half* xsh = reinterpret_cast<__half*>(smc);
    uint4* whl = reinterpret_cast<uint4*>(smc + 36864);            // [2048]
    float4* W2s = reinterpret_cast<float4*>(smc + 36864 + 32768);  // [128]
    float* b1s = reinterpret_cast<float*>(smc + 36864 + 32768 + 2048);  // [128]

    int t = threadIdx.x;
    int lane = t & 31;
    int w = t >> 5;
    int wblk = w * WBLK_H;

    for (int i = t; i < 2048; i += 256) whl[i] = g_W1[i];
    if (t < HID) { W2s[t] = reinterpret_cast<const float4*>(W2)[t]; b1s[t] = b1[t]; }
    __syncthreads();

    LDM_ROLE(lane, rowoff, koff)
    uint32_t aHi = (uint32_t)__cvta_generic_to_shared(xsh) +
                   (unsigned)(wblk + rowoff * SP + koff) * 2u;

    float4 b2v = *reinterpret_cast<const float4*>(b2);
    int warpId = blockIdx.x * 8 + w;
    const int NWP = GRID * 8;
    int tiles = (NN + 15) / 16;
    const float4* in4 = reinterpret_cast<const float4*>(C);
    int r = lane >> 2, c = lane & 3;

    for (int wt = warpId; wt < tiles; wt += NWP) {
        int n0 = wt * 16;
        int bi = n0 + (lane & 15);
        int bval = batch[bi < NN ? bi : NN - 1];
        __syncwarp();
#pragma unroll
        for (int it = 0; it < 8; it++) {
            int j = it * 32 + lane;
            int e = j >> 4;
            int k4 = j & 15;
            float4 v = make_float4(0.f, 0.f, 0.f, 0.f);
            if (n0 + e < NN) v = in4[(size_t)(n0 + e) * 16 + k4];
            uint2 hi, lo;
            split4(v, hi, lo);
            *reinterpret_cast<uint2*>(&xsh[wblk + e * SP + k4 * 4]) = hi;
            *reinterpret_cast<uint2*>(&xsh[wblk + 1152 + e * SP + k4 * 4]) = lo;
        }
        __syncwarp();

        float o[2][4];
#pragma unroll
        for (int i = 0; i < 2; i++)
#pragma unroll
            for (int q = 0; q < 4; q++) o[i][q] = 0.0f;

#pragma unroll
        for (int hf = 0; hf < 2; hf++) {
            float acc[8][4];
            ZERO_ACC(acc)
            mma_mainloop(aHi, whl + hf * 1024, lane, acc);
#pragma unroll
            for (int nt = 0; nt < 8; nt++) {
                int col = hf * 64 + nt * 8 + 2 * c;
                float t0 = fast_tanh(acc[nt][0] + b1s[col]);
                float t1 = fast_tanh(acc[nt][1] + b1s[col + 1]);
                float t2 = fast_tanh(acc[nt][2] + b1s[col]);
                float t3 = fast_tanh(acc[nt][3] + b1s[col + 1]);
                float4 wa = W2s[col];
                float4 wc = W2s[col + 1];
                o[0][0] += t0 * wa.x + t1 * wc.x;
                o[0][1] += t0 * wa.y + t1 * wc.y;
                o[0][2] += t0 * wa.z + t1 * wc.z;
                o[0][3] += t0 * wa.w + t1 * wc.w;
                o[1][0] += t2 * wa.x + t3 * wc.x;
                o[1][1] += t2 * wa.y + t3 * wc.y;
                o[1][2] += t2 * wa.z + t3 * wc.z;
                o[1][3] += t2 * wa.w + t3 * wc.w;
            }
        }
#pragma unroll
        for (int i = 0; i < 2; i++)
#pragma unroll
            for (int q = 0; q < 4; q++) {
                o[i][q] += __shfl_xor_sync(0xffffffffu, o[i][q], 1);
                o[i][q] += __shfl_xor_sync(0xffffffffu, o[i][q], 2);
            }
        int g0 = __shfl_sync(0xffffffffu, bval, r);
        int g1 = __shfl_sync(0xffffffffu, bval, r + 8);
        if (c == 0) {
            if (n0 + r < NN)
                red_add_v4(out + (size_t)g0 * 4,
                           o[0][0] + b2v.x, o[0][1] + b2v.y,
                           o[0][2] + b2v.z, o[0][3] + b2v.w);
            if (n0 + r + 8 < NN)
                red_add_v4(out + (size_t)g1 * 4,
                           o[1][0] + b2v.x, o[1][1] + b2v.y,
                           o[1][2] + b2v.z, o[1][3] + b2v.w);
        }
    }
}

extern "C" void kernel_launch(void* const* d_in, const int* in_sizes, int n_in,
                              void* d_out, int out_size) {
    const int*   Z         = (const int*)d_in[0];
    const int*   ei        = (const int*)d_in[1];
    const float* edge_attr = (const float*)d_in[2];
    const int*   batch     = (const int*)d_in[3];
    const float* embed     = (const float*)d_in[4];
    const float* cfW       = (const float*)d_in[5];
    const float* cfb       = (const float*)d_in[6];
    const float* dfW       = (const float*)d_in[7];
    const float* dfb       = (const float*)d_in[8];
    const float* fcW       = (const float*)d_in[9];
    const float* W1        = (const float*)d_in[10];
    const float* b1        = (const float*)d_in[11];
    const float* W2        = (const float*)d_in[12];
    const float* b2        = (const float*)d_in[13];
    const int* src = ei;
    const int* dst = ei + NE;

    float *Ca, *nf;
    __half* dfeat;
    cudaGetSymbolAddress((void**)&Ca, g_Ca);
    cudaGetSymbolAddress((void**)&nf, g_nf);
    cudaGetSymbolAddress((void**)&dfeat, g_dfeat);

    const int SM_GEMM = 36864 + 16384 + 256;            // 53504
    const int SM_EDGE = 36864 + 8192;                    // 45056
    const int SM_RO   = 36864 + 32768 + 2048 + 512;      // 72192
    cudaFuncSetAttribute(k_dfeat, cudaFuncAttributeMaxDynamicSharedMemorySize, SM_GEMM);
    cudaFuncSetAttribute(k_nodemv, cudaFuncAttributeMaxDynamicSharedMemorySize, SM_GEMM);
    cudaFuncSetAttribute(k_edge, cudaFuncAttributeMaxDynamicSharedMemorySize, SM_EDGE);
    cudaFuncSetAttribute(k_readout, cudaFuncAttributeMaxDynamicSharedMemorySize, SM_RO);

    k_prep<<<1, 256>>>(fcW, dfW, cfW, W1);
    k_init_C<<<(NN * BASIS + 255) / 256, 256>>>(Z, embed, Ca);
    k_dfeat<<<GRID, 256, SM_GEMM>>>(edge_attr, dfb, dfeat);

    for (int t = 0; t < 3; t++) {
        k_nodemv<<<GRID, 256, SM_GEMM>>>(Ca, cfb, nf);
        k_edge<<<GRID, 256, SM_EDGE>>>(nf, dfeat, src, dst, Ca);
    }

    k_zero<<<(NG * 4 + 255) / 256, 256>>>((float*)d_out, NG * 4);
    k_readout<<<GRID, 256, SM_RO>>>(Ca, batch, b1, W2, b2, (float*)d_out);
}

// round 17
// speedup vs baseline: 1.1630x; 1.0493x over previous
#include <cuda_runtime.h>
#include <cuda_fp16.h>
#include <cstdint>
#include <cstddef>

#define NN 50000
#define NE 800000
#define BASIS 64
#define HID 128
#define NG 512
#define SP 72            // smem stride in halves (144B rows)
#define WBLK_H 2304      // halves per warp block (hi 1152 + lo 1152) = 4608 bytes
#define GRID 444         // persistent: 3 blocks per SM

// Scratch (__device__ globals per allocation rules).
__device__ __align__(256) __half g_dfeat[(size_t)NE * BASIS];   // fp16 dfeat (102MB)
__device__ __align__(256) float g_nf[(size_t)NN * BASIS];
__device__ __align__(256) float g_Ca[(size_t)NN * BASIS];
// hi-only fp16 B-fragment tables (2-product GEMMs): [kc 4][nt 8][lane 32] -> uint2
__device__ __align__(256) uint2 g_fcW2[1024];
__device__ __align__(256) uint2 g_dfW2[1024];
__device__ __align__(256) uint2 g_cfW2[1024];
// W1 keeps full hi/lo (3-product readout): uint4, two 64-col halves
__device__ __align__(256) uint4 g_W1[2048];

__device__ __forceinline__ float fast_tanh(float v) {
    float y;
    asm("tanh.approx.f32 %0, %1;" : "=f"(y) : "f"(v));
    return y;
}
__device__ __forceinline__ void red_add_v4(float* p, float a, float b, float c, float d) {
    asm volatile("red.global.add.v4.f32 [%0], {%1, %2, %3, %4};"
                 :: "l"(p), "f"(a), "f"(b), "f"(c), "f"(d) : "memory");
}
__device__ __forceinline__ unsigned pack_h2(float x, float y) {
    __half2 h = __floats2half2_rn(x, y);
    return *reinterpret_cast<unsigned*>(&h);
}
__device__ __forceinline__ unsigned split_hi(float2 v, float2& rest) {
    __half2 h = __floats2half2_rn(v.x, v.y);
    rest.x = v.x - __low2float(h);
    rest.y = v.y - __high2float(h);
    return *reinterpret_cast<unsigned*>(&h);
}
__device__ __forceinline__ void split4(float4 v, uint2& hi, uint2& lo) {
    float2 r01, r23;
    unsigned h01 = split_hi(make_float2(v.x, v.y), r01);
    unsigned h23 = split_hi(make_float2(v.z, v.w), r23);
    hi = make_uint2(h01, h23);
    lo = make_uint2(pack_h2(r01.x, r01.y), pack_h2(r23.x, r23.y));
}
__device__ __forceinline__ void mma_fp16(float* d, const unsigned* a, unsigned bx, unsigned by) {
    asm volatile(
        "mma.sync.aligned.m16n8k16.row.col.f32.f16.f16.f32 "
        "{%0,%1,%2,%3}, {%4,%5,%6,%7}, {%8,%9}, {%0,%1,%2,%3};"
        : "+f"(d[0]), "+f"(d[1]), "+f"(d[2]), "+f"(d[3])
        : "r"(a[0]), "r"(a[1]), "r"(a[2]), "r"(a[3]), "r"(bx), "r"(by));
}
__device__ __forceinline__ void ldm_x4(uint32_t addr, unsigned r[4]) {
    asm volatile("ldmatrix.sync.aligned.m8n8.x4.shared.b16 {%0,%1,%2,%3}, [%4];"
                 : "=r"(r[0]), "=r"(r[1]), "=r"(r[2]), "=r"(r[3]) : "r"(addr));
}

// Build fragment tables: hi-only uint2 for fcW/dfW/cfW, hi/lo uint4 for W1.
__global__ void __launch_bounds__(256) k_prep(const float* __restrict__ fcW,
                                              const float* __restrict__ dfW,
                                              const float* __restrict__ cfW,
                                              const float* __restrict__ W1) {
    for (int idx = threadIdx.x; idx < 1024; idx += 256) {
        int kc = idx >> 8;
        int nt = (idx >> 5) & 7;
        int lane = idx & 31;
        int n = nt * 8 + (lane >> 2);
        int k0 = kc * 16 + (lane & 3) * 2;
        const float* Ws[3] = {fcW, dfW, cfW};
        uint2* T[3] = {g_fcW2, g_dfW2, g_cfW2};
#pragma unroll
        for (int w = 0; w < 3; w++) {
            uint2 e;
            e.x = pack_h2(Ws[w][(k0 + 0) * BASIS + n], Ws[w][(k0 + 1) * BASIS + n]);
            e.y = pack_h2(Ws[w][(k0 + 8) * BASIS + n], Ws[w][(k0 + 9) * BASIS + n]);
            T[w][idx] = e;
        }
    }
    for (int idx = threadIdx.x; idx < 2048; idx += 256) {
        int hf = idx >> 10;
        int rest = idx & 1023;
        int kc = rest >> 8;
        int nt = (rest >> 5) & 7;
        int lane = rest & 31;
        int n = hf * 64 + nt * 8 + (lane >> 2);
        int k0 = kc * 16 + (lane & 3) * 2;
        float w00 = W1[(k0 + 0) * HID + n];
        float w01 = W1[(k0 + 1) * HID + n];
        float w10 = W1[(k0 + 8) * HID + n];
        float w11 = W1[(k0 + 9) * HID + n];
        float2 r0, r1;
        uint4 e;
        e.x = split_hi(make_float2(w00, w01), r0);
        e.y = split_hi(make_float2(w10, w11), r1);
        e.z = pack_h2(r0.x, r0.y);
        e.w = pack_h2(r1.x, r1.y);
        g_W1[idx] = e;
    }
}

__global__ void __launch_bounds__(256) k_init_C(const int* __restrict__ Z,
                                                const float* __restrict__ embed,
                                                float* __restrict__ C) {
    int idx = blockIdx.x * blockDim.x + threadIdx.x;
    if (idx >= NN * BASIS) return;
    C[idx] = embed[Z[idx >> 6] * BASIS + (idx & 63)];
}

__global__ void __launch_bounds__(256) k_zero(float* __restrict__ p, int n) {
    int i = blockIdx.x * blockDim.x + threadIdx.x;
    if (i < n) p[i] = 0.0f;
}

// ---------------------------------------------------------------------------
// ldmatrix mainloops, 16-row warp tile.
// 3-product (hi/lo W, uint4) for readout; 2-product (hi-only W, uint2) else.
// ---------------------------------------------------------------------------
__device__ __forceinline__ void mma_mainloop3(uint32_t aHi,
                                              const uint4* __restrict__ whl,
                                              int lane, float acc[8][4]) {
    uint32_t aLo = aHi + (unsigned)(1152 * 2);
#pragma unroll
    for (int kc = 0; kc < 4; kc++) {
        unsigned ah[4], al[4];
        uint32_t off = (unsigned)(kc * 16) * 2u;
        ldm_x4(aHi + off, ah);
        ldm_x4(aLo + off, al);
#pragma unroll
        for (int nt = 0; nt < 8; nt++) {
            uint4 wv = whl[(kc * 8 + nt) * 32 + lane];
            mma_fp16(acc[nt], ah, wv.x, wv.y);
            mma_fp16(acc[nt], al, wv.x, wv.y);
            mma_fp16(acc[nt], ah, wv.z, wv.w);
        }
    }
}

__device__ __forceinline__ void mma_mainloop2(uint32_t aHi,
                                              const uint2* __restrict__ wh,
                                              int lane, float acc[8][4]) {
    uint32_t aLo = aHi + (unsigned)(1152 * 2);
#pragma unroll
    for (int kc = 0; kc < 4; kc++) {
        unsigned ah[4], al[4];
        uint32_t off = (unsigned)(kc * 16) * 2u;
        ldm_x4(aHi + off, ah);
        ldm_x4(aLo + off, al);
#pragma unroll
        for (int nt = 0; nt < 8; nt++) {
            uint2 wv = wh[(kc * 8 + nt) * 32 + lane];
            mma_fp16(acc[nt], ah, wv.x, wv.y);
            mma_fp16(acc[nt], al, wv.x, wv.y);
        }
    }
}

#define ZERO_ACC(acc)                               \
    _Pragma("unroll")                               \
    for (int nt = 0; nt < 8; nt++)                  \
        _Pragma("unroll")                           \
        for (int q = 0; q < 4; q++) acc[nt][q] = 0.0f;

#define LDM_ROLE(lane, rowoff, koff)                 \
    int rowoff = ((lane >> 3) & 1) * 8 + (lane & 7); \
    int koff = ((lane >> 4) & 1) * 8;

// Persistent tiled row-GEMM (2-product): out = in @ W + bias.
template<bool OUT_HALF>
__device__ __forceinline__ void rowgemm_body(const float* __restrict__ in,
                                             const uint2* __restrict__ gW,
                                             const float* __restrict__ bias,
                                             void* __restrict__ out,
                                             int nrows) {
    extern __shared__ char smc[];
    __half* xsh = reinterpret_cast<__half*>(smc);                 // 8 warp blocks x 4608B
    uint2* wh = reinterpret_cast<uint2*>(smc + 36864);            // [1024] 8KB
    float* bs = reinterpret_cast<float*>(smc + 36864 + 8192);     // [64]

    int t = threadIdx.x;
    int lane = t & 31;
    int w = t >> 5;
    int wblk = w * WBLK_H;
    float* fs = reinterpret_cast<float*>(smc + w * (WBLK_H * 2)); // warp-own 16x68 floats

    for (int i = t; i < 1024; i += 256) wh[i] = gW[i];
    if (t < BASIS) bs[t] = bias[t];
    __syncthreads();

    LDM_ROLE(lane, rowoff, koff)
    uint32_t aHi = (uint32_t)__cvta_generic_to_shared(xsh) +
                   (unsigned)(wblk + rowoff * SP + koff) * 2u;

    int warpId = blockIdx.x * 8 + w;
    const int NWP = GRID * 8;
    int tiles = (nrows + 15) / 16;
    const float4* in4 = reinterpret_cast<const float4*>(in);
    float4* o4 = reinterpret_cast<float4*>(out);
    uint2* o2 = reinterpret_cast<uint2*>(out);
    int r = lane >> 2, c = lane & 3;

    for (int wt = warpId; wt < tiles; wt += NWP) {
        int n0 = wt * 16;
        __syncwarp();
#pragma unroll
        for (int it = 0; it < 8; it++) {
            int j = it * 32 + lane;
            int e = j >> 4;
            int k4 = j & 15;
            float4 v = make_float4(0.f, 0.f, 0.f, 0.f);
            if (n0 + e < nrows) v = in4[(size_t)(n0 + e) * 16 + k4];
            uint2 hi, lo;
            split4(v, hi, lo);
            *reinterpret_cast<uint2*>(&xsh[wblk + e * SP + k4 * 4]) = hi;
            *reinterpret_cast<uint2*>(&xsh[wblk + 1152 + e * SP + k4 * 4]) = lo;
        }
        __syncwarp();

        float acc[8][4];
        ZERO_ACC(acc)
        mma_mainloop2(aHi, wh, lane, acc);
        __syncwarp();

#pragma unroll
        for (int nt = 0; nt < 8; nt++) {
            int col = nt * 8 + 2 * c;
            float b0 = bs[col], b1 = bs[col + 1];
            *reinterpret_cast<float2*>(&fs[r * 68 + col]) =
                make_float2(acc[nt][0] + b0, acc[nt][1] + b1);
            *reinterpret_cast<float2*>(&fs[(r + 8) * 68 + col]) =
                make_float2(acc[nt][2] + b0, acc[nt][3] + b1);
        }
        __syncwarp();

#pragma unroll
        for (int it = 0; it < 8; it++) {
            int j = it * 32 + lane;
            int e = j >> 4;
            int k4 = j & 15;
            if (n0 + e < nrows) {
                float4 v = *reinterpret_cast<const float4*>(&fs[e * 68 + (k4 << 2)]);
                if (OUT_HALF) {
                    uint2 h;
                    h.x = pack_h2(v.x, v.y);
                    h.y = pack_h2(v.z, v.w);
                    o2[(size_t)(n0 + e) * 16 + k4] = h;
                } else {
                    o4[(size_t)(n0 + e) * 16 + k4] = v;
                }
            }
        }
    }
}

__global__ void __launch_bounds__(256, 3) k_dfeat(const float* __restrict__ in,
                                                  const float* __restrict__ bias,
                                                  __half* __restrict__ out) {
    rowgemm_body<true>(in, g_dfW2, bias, out, NE);
}

__global__ void __launch_bounds__(256, 3) k_nodemv(const float* __restrict__ C,
                                                   const float* __restrict__ bias,
                                                   float* __restrict__ out) {
    rowgemm_body<false>(C, g_cfW2, bias, out, NN);
}

// Edge kernel: C[dst] += tanh( (nf[src] * dfeat) @ fcW ), dfeat fp16, 2-product.
__global__ void __launch_bounds__(256, 3) k_edge(const float* __restrict__ nf,
                                                 const __half* __restrict__ dfeat,
                                                 const int* __restrict__ src,
                                                 const int* __restrict__ dst,
                                                 float* __restrict__ Cout) {
    extern __shared__ char smc[];
    __half* xsh = reinterpret_cast<__half*>(smc);
    uint2* wh = reinterpret_cast<uint2*>(smc + 36864);   // [1024] (8KB)

    int t = threadIdx.x;
    int lane = t & 31;
    int w = t >> 5;
    int wblk = w * WBLK_H;

    for (int i = t; i < 1024; i += 256) wh[i] = g_fcW2[i];
    __syncthreads();

    LDM_ROLE(lane, rowoff, koff)
    uint32_t aHi = (uint32_t)__cvta_generic_to_shared(xsh) +
                   (unsigned)(wblk + rowoff * SP + koff) * 2u;

    int warpId = blockIdx.x * 8 + w;
    const int NWP = GRID * 8;
    const int tiles = NE / 16;   // 50000 exact
    const float4* nf4 = reinterpret_cast<const float4*>(nf);
    const uint2* df2 = reinterpret_cast<const uint2*>(dfeat);
    int r = lane >> 2, c = lane & 3;

    int wt = warpId;
    int sval = 0, dval = 0;
    if (wt < tiles) {
        sval = src[(size_t)wt * 16 + (lane & 15)];
        dval = dst[(size_t)wt * 16 + (lane & 15)];
    }
    for (; wt < tiles; wt += NWP) {
        int wn = wt + NWP;
        int sv_n = 0, dv_n = 0;
        if (wn < tiles) {
            sv_n = src[(size_t)wn * 16 + (lane & 15)];
            dv_n = dst[(size_t)wn * 16 + (lane & 15)];
        }
        __syncwarp();
#pragma unroll
        for (int it = 0; it < 8; it++) {
            int j = it * 32 + lane;
            int er = j >> 4;
            int k4 = j & 15;
            int s = __shfl_sync(0xffffffffu, sval, er);
            float4 a = nf4[(size_t)s * 16 + k4];
            uint2 bh = df2[((size_t)wt * 16 + er) * 16 + k4];
            float2 f01 = __half22float2(*reinterpret_cast<__half2*>(&bh.x));
            float2 f23 = __half22float2(*reinterpret_cast<__half2*>(&bh.y));
            float4 v = make_float4(a.x * f01.x, a.y * f01.y, a.z * f23.x, a.w * f23.y);
            uint2 hi, lo;
            split4(v, hi, lo);
            *reinterpret_cast<uint2*>(&xsh[wblk + er * SP + k4 * 4]) = hi;
            *reinterpret_cast<uint2*>(&xsh[wblk + 1152 + er * SP + k4 * 4]) = lo;
        }
        __syncwarp();

        float acc[8][4];
        ZERO_ACC(acc)
        mma_mainloop2(aHi, wh, lane, acc);

        int dA = __shfl_sync(0xffffffffu, dval, r);
        int dB = __shfl_sync(0xffffffffu, dval, r + 8);
        float* pA = Cout + (size_t)dA * BASIS;
        float* pB = Cout + (size_t)dB * BASIS;
#pragma unroll
        for (int nt = 0; nt < 8; nt++) {
            float t0 = fast_tanh(acc[nt][0]);
            float t1 = fast_tanh(acc[nt][1]);
            float t2 = fast_tanh(acc[nt][2]);
            float t3 = fast_tanh(acc[nt][3]);
            float p0 = __shfl_xor_sync(0xffffffffu, t0, 1);
            float p1 = __shfl_xor_sync(0xffffffffu, t1, 1);
            float p2 = __shfl_xor_sync(0xffffffffu, t2, 1);
            float p3 = __shfl_xor_sync(0xffffffffu, t3, 1);
            if ((lane & 1) == 0) {
                int col = nt * 8 + 2 * c;   // c even here
                red_add_v4(pA + col, t0, t1, p0, p1);
                red_add_v4(pB + col, t2, t3, p2, p3);
            }
        }
        sval = sv_n;
        dval = dv_n;
    }
}

// Readout: out[batch[n]] += tanh(C@W1+b1)@W2 + b2  (3-product, W1 hi/lo)
__global__ void __launch_bounds__(256, 3) k_readout(const float* __restrict__ C,
                                                    const int* __restrict__ batch,
                                                    const float* __restrict__ b1,
                                                    const float* __restrict__ W2,
                                                    const float* __restrict__ b2,
                                                    float* __restrict__ out) {
    extern __shared__ char smc[];
    __half* xsh = reinterpret_cast<__half*>(smc);
    uint4* whl = reinterpret_cast<uint4*>(smc + 36864);            // [2048]
    float4* W2s = reinterpret_cast<float4*>(smc + 36864 + 32768);  // [128]
    float* b1s = reinterpret_cast<float*>(smc + 36864 + 32768 + 2048);  // [128]

    int t = threadIdx.x;
    int lane = t & 31;
    int w = t >> 5;
    int wblk = w * WBLK_H;

    for (int i = t; i < 2048; i += 256) whl[i] = g_W1[i];
    if (t < HID) { W2s[t] = reinterpret_cast<const float4*>(W2)[t]; b1s[t] = b1[t]; }
    __syncthreads();

    LDM_ROLE(lane, rowoff, koff)
    uint32_t aHi = (uint32_t)__cvta_generic_to_shared(xsh) +
                   (unsigned)(wblk + rowoff * SP + koff) * 2u;

    float4 b2v = *reinterpret_cast<const float4*>(b2);
    int warpId = blockIdx.x * 8 + w;
    const int NWP = GRID * 8;
    int tiles = (NN + 15) / 16;
    const float4* in4 = reinterpret_cast<const float4*>(C);
    int r = lane >> 2, c = lane & 3;

    for (int wt = warpId; wt < tiles; wt += NWP) {
        int n0 = wt * 16;
        int bi = n0 + (lane & 15);
        int bval = batch[bi < NN ? bi : NN - 1];
        __syncwarp();
#pragma unroll
        for (int it = 0; it < 8; it++) {
            int j = it * 32 + lane;
            int e = j >> 4;
            int k4 = j & 15;
            float4 v = make_float4(0.f, 0.f, 0.f, 0.f);
            if (n0 + e < NN) v = in4[(size_t)(n0 + e) * 16 + k4];
            uint2 hi, lo;
            split4(v, hi, lo);
            *reinterpret_cast<uint2*>(&xsh[wblk + e * SP + k4 * 4]) = hi;
            *reinterpret_cast<uint2*>(&xsh[wblk + 1152 + e * SP + k4 * 4]) = lo;
        }
        __syncwarp();

        float o[2][4];
#pragma unroll
        for (int i = 0; i < 2; i++)
#pragma unroll
            for (int q = 0; q < 4; q++) o[i][q] = 0.0f;

#pragma unroll
        for (int hf = 0; hf < 2; hf++) {
            float acc[8][4];
            ZERO_ACC(acc)
            mma_mainloop3(aHi, whl + hf * 1024, lane, acc);
#pragma unroll
            for (int nt = 0; nt < 8; nt++) {
                int col = hf * 64 + nt * 8 + 2 * c;
                float t0 = fast_tanh(acc[nt][0] + b1s[col]);
                float t1 = fast_tanh(acc[nt][1] + b1s[col + 1]);
                float t2 = fast_tanh(acc[nt][2] + b1s[col]);
                float t3 = fast_tanh(acc[nt][3] + b1s[col + 1]);
                float4 wa = W2s[col];
                float4 wc = W2s[col + 1];
                o[0][0] += t0 * wa.x + t1 * wc.x;
                o[0][1] += t0 * wa.y + t1 * wc.y;
                o[0][2] += t0 * wa.z + t1 * wc.z;
                o[0][3] += t0 * wa.w + t1 * wc.w;
                o[1][0] += t2 * wa.x + t3 * wc.x;
                o[1][1] += t2 * wa.y + t3 * wc.y;
                o[1][2] += t2 * wa.z + t3 * wc.z;
                o[1][3] += t2 * wa.w + t3 * wc.w;
            }
        }
#pragma unroll
        for (int i = 0; i < 2; i++)
#pragma unroll
            for (int q = 0; q < 4; q++) {
                o[i][q] += __shfl_xor_sync(0xffffffffu, o[i][q], 1);
                o[i][q] += __shfl_xor_sync(0xffffffffu, o[i][q], 2);
            }
        int g0 = __shfl_sync(0xffffffffu, bval, r);
        int g1 = __shfl_sync(0xffffffffu, bval, r + 8);
        if (c == 0) {
            if (n0 + r < NN)
                red_add_v4(out + (size_t)g0 * 4,
                           o[0][0] + b2v.x, o[0][1] + b2v.y,
                           o[0][2] + b2v.z, o[0][3] + b2v.w);
            if (n0 + r + 8 < NN)
                red_add_v4(out + (size_t)g1 * 4,
                           o[1][0] + b2v.x, o[1][1] + b2v.y,
                           o[1][2] + b2v.z, o[1][3] + b2v.w);
        }
    }
}

extern "C" void kernel_launch(void* const* d_in, const int* in_sizes, int n_in,
                              void* d_out, int out_size) {
    const int*   Z         = (const int*)d_in[0];
    const int*   ei        = (const int*)d_in[1];
    const float* edge_attr = (const float*)d_in[2];
    const int*   batch     = (const int*)d_in[3];
    const float* embed     = (const float*)d_in[4];
    const float* cfW       = (const float*)d_in[5];
    const float* cfb       = (const float*)d_in[6];
    const float* dfW       = (const float*)d_in[7];
    const float* dfb       = (const float*)d_in[8];
    const float* fcW       = (const float*)d_in[9];
    const float* W1        = (const float*)d_in[10];
    const float* b1        = (const float*)d_in[11];
    const float* W2        = (const float*)d_in[12];
    const float* b2        = (const float*)d_in[13];
    const int* src = ei;
    const int* dst = ei + NE;

    float *Ca, *nf;
    __half* dfeat;
    cudaGetSymbolAddress((void**)&Ca, g_Ca);
    cudaGetSymbolAddress((void**)&nf, g_nf);
    cudaGetSymbolAddress((void**)&dfeat, g_dfeat);

    const int SM_GEMM = 36864 + 8192 + 256;             // 45312
    const int SM_EDGE = 36864 + 8192;                    // 45056
    const int SM_RO   = 36864 + 32768 + 2048 + 512;      // 72192
    cudaFuncSetAttribute(k_dfeat, cudaFuncAttributeMaxDynamicSharedMemorySize, SM_GEMM);
    cudaFuncSetAttribute(k_nodemv, cudaFuncAttributeMaxDynamicSharedMemorySize, SM_GEMM);
    cudaFuncSetAttribute(k_edge, cudaFuncAttributeMaxDynamicSharedMemorySize, SM_EDGE);
    cudaFuncSetAttribute(k_readout, cudaFuncAttributeMaxDynamicSharedMemorySize, SM_RO);

    k_prep<<<1, 256>>>(fcW, dfW, cfW, W1);
    k_init_C<<<(NN * BASIS + 255) / 256, 256>>>(Z, embed, Ca);
    k_dfeat<<<GRID, 256, SM_GEMM>>>(edge_attr, dfb, dfeat);

    for (int t = 0; t < 3; t++) {
        k_nodemv<<<GRID, 256, SM_GEMM>>>(Ca, cfb, nf);
        k_edge<<<GRID, 256, SM_EDGE>>>(nf, dfeat, src, dst, Ca);
    }

    k_zero<<<(NG * 4 + 255) / 256, 256>>>((float*)d_out, NG * 4);
    k_readout<<<GRID, 256, SM_RO>>>(Ca, batch, b1, W2, b2, (float*)d_out);
}